// round 1
// baseline (speedup 1.0000x reference)
#include <cuda_runtime.h>
#include <cstdint>
#include <cstddef>

// Problem shape (fixed)
#define BB 8
#define NN 4096
#define EE 2048
#define CC 128

// Scratch (no cudaMalloc allowed)
__device__ float g_Z[BB * EE * CC];   // z/se  (scaled v2e aggregate, pre-projection)
__device__ float g_E[BB * EE * CC];   // e     (edge features)
__device__ float g_SE[BB * EE];       // se    (edge degree)

// GEMM tiling
#define BM 128
#define BN 128
#define BK 32
#define LDKM 136   // As stored [k][m], pad 8 -> conflict-free a-frag loads
#define LDMK 36    // As stored [m][k], pad 4 -> conflict-free a-frag loads
#define LDB_ 136   // Bs stored [k][n], pad 8 -> conflict-free b-frag loads

__device__ __forceinline__ float tf32r(float x) {
    // round-to-nearest tf32 (unbiased; truncation bias would blow the error budget)
    uint32_t u;
    asm("cvt.rna.tf32.f32 %0, %1;" : "=r"(u) : "f"(x));
    return __uint_as_float(u);
}

__device__ __forceinline__ void mma8(float& d0, float& d1, float& d2, float& d3,
                                     uint32_t a0, uint32_t a1, uint32_t a2, uint32_t a3,
                                     uint32_t b0, uint32_t b1) {
    asm volatile(
        "mma.sync.aligned.m16n8k8.row.col.f32.tf32.tf32.f32 "
        "{%0,%1,%2,%3},{%4,%5,%6,%7},{%8,%9},{%0,%1,%2,%3};"
        : "+f"(d0), "+f"(d1), "+f"(d2), "+f"(d3)
        : "r"(a0), "r"(a1), "r"(a2), "r"(a3), "r"(b0), "r"(b1));
}

// ===========================================================================
// S1: z[b,e,:] = sum_n H[b,n,e] * x[b,n,:]   (A = H^T, K-major in gmem)
//     se[b,e]  = sum_n H[b,n,e]              (free from A-fragments)
//     g_Z stores z/se (guarded), g_SE stores se.
// ===========================================================================
__global__ void __launch_bounds__(256, 1)
s1_kernel(const float* __restrict__ H, const float* __restrict__ X) {
    const int b  = blockIdx.y;
    const int e0 = blockIdx.x * BM;

    extern __shared__ float sm[];
    float* As = sm;                       // 2 * BK * LDKM  ([k][m])
    float* Bs = sm + 2 * BK * LDKM;       // 2 * BK * LDB_  ([k][n])
    __shared__ float s_rs[BM];
    __shared__ float s_inv[BM];

    const int tid = threadIdx.x;
    const int lane = tid & 31, wid = tid >> 5;
    const int g = lane >> 2, tg = lane & 3;
    const int wm = (wid >> 1) * 32;
    const int wn = (wid & 1) * 64;

    const float* Hb = H + (size_t)b * NN * EE;
    const float* Xb = X + (size_t)b * NN * CC;

    float acc[2][8][4];
#pragma unroll
    for (int i = 0; i < 2; i++)
#pragma unroll
        for (int j = 0; j < 8; j++)
#pragma unroll
            for (int k = 0; k < 4; k++) acc[i][j][k] = 0.f;
    float rs[2][2] = {{0.f, 0.f}, {0.f, 0.f}};

    float4 ar[4], br[4];

    auto LDGA = [&](int n0) {
#pragma unroll
        for (int i = 0; i < 4; i++) {
            int idx = tid + i * 256;
            int k = idx >> 5, m4 = idx & 31;
            ar[i] = *reinterpret_cast<const float4*>(Hb + (size_t)(n0 + k) * EE + e0 + m4 * 4);
        }
    };
    auto LDGB = [&](int n0) {
#pragma unroll
        for (int i = 0; i < 4; i++) {
            int idx = tid + i * 256;
            int k = idx >> 5, c4 = idx & 31;
            br[i] = *reinterpret_cast<const float4*>(Xb + (size_t)(n0 + k) * CC + c4 * 4);
        }
    };
    auto STS = [&](int buf) {
        float* Ad = As + buf * BK * LDKM;
        float* Bd = Bs + buf * BK * LDB_;
#pragma unroll
        for (int i = 0; i < 4; i++) {
            int idx = tid + i * 256;
            int k = idx >> 5, m4 = idx & 31;
            *reinterpret_cast<float4*>(Ad + k * LDKM + m4 * 4) = ar[i];  // H exact, no cvt
            float4 v = br[i];
            v.x = tf32r(v.x); v.y = tf32r(v.y); v.z = tf32r(v.z); v.w = tf32r(v.w);
            *reinterpret_cast<float4*>(Bd + k * LDB_ + m4 * 4) = v;
        }
    };
    auto COMPUTE = [&](int buf) {
        const float* Ab = As + buf * BK * LDKM;
        const float* Bb = Bs + buf * BK * LDB_;
#pragma unroll
        for (int kk = 0; kk < BK; kk += 8) {
            uint32_t af[2][4];
#pragma unroll
            for (int mt = 0; mt < 2; mt++) {
                const float* ap = Ab + (kk + tg) * LDKM + wm + mt * 16 + g;
                af[mt][0] = __float_as_uint(ap[0]);
                af[mt][1] = __float_as_uint(ap[8]);
                af[mt][2] = __float_as_uint(ap[4 * LDKM]);
                af[mt][3] = __float_as_uint(ap[4 * LDKM + 8]);
            }
            if ((wid & 1) == 0) {  // count each H element once (wn==0 warps)
#pragma unroll
                for (int mt = 0; mt < 2; mt++) {
                    rs[mt][0] += __uint_as_float(af[mt][0]) + __uint_as_float(af[mt][2]);
                    rs[mt][1] += __uint_as_float(af[mt][1]) + __uint_as_float(af[mt][3]);
                }
            }
#pragma unroll
            for (int nt = 0; nt < 8; nt++) {
                const float* bp = Bb + (kk + tg) * LDB_ + wn + nt * 8 + g;
                uint32_t b0 = __float_as_uint(bp[0]);
                uint32_t b1 = __float_as_uint(bp[4 * LDB_]);
                mma8(acc[0][nt][0], acc[0][nt][1], acc[0][nt][2], acc[0][nt][3],
                     af[0][0], af[0][1], af[0][2], af[0][3], b0, b1);
                mma8(acc[1][nt][0], acc[1][nt][1], acc[1][nt][2], acc[1][nt][3],
                     af[1][0], af[1][1], af[1][2], af[1][3], b0, b1);
            }
        }
    };

    LDGA(0); LDGB(0); STS(0); __syncthreads();
    int buf = 0;
    const int KT = NN / BK;
    for (int kt = 0; kt < KT; kt++) {
        if (kt + 1 < KT) { LDGA((kt + 1) * BK); LDGB((kt + 1) * BK); }
        COMPUTE(buf);
        if (kt + 1 < KT) {
            STS(buf ^ 1);
            __syncthreads();
            buf ^= 1;
        }
    }

    // se: quad-reduce row sums
    if ((wid & 1) == 0) {
#pragma unroll
        for (int mt = 0; mt < 2; mt++)
#pragma unroll
            for (int j = 0; j < 2; j++) {
                float v = rs[mt][j];
                v += __shfl_xor_sync(0xffffffff, v, 1);
                v += __shfl_xor_sync(0xffffffff, v, 2);
                if (tg == 0) s_rs[wm + mt * 16 + j * 8 + g] = v;
            }
    }
    __syncthreads();
    if (tid < BM) {
        float s = s_rs[tid];
        g_SE[b * EE + e0 + tid] = s;
        s_inv[tid] = (s > 0.f) ? (1.0f / s) : 0.f;
    }
    __syncthreads();

#pragma unroll
    for (int mt = 0; mt < 2; mt++) {
        int r0 = wm + mt * 16 + g;
        float i0 = s_inv[r0], i1 = s_inv[r0 + 8];
        float* z0 = g_Z + ((size_t)(b * EE + e0 + r0)) * CC;
#pragma unroll
        for (int nt = 0; nt < 8; nt++) {
            int col = wn + nt * 8 + 2 * tg;
            float2 v0 = make_float2(acc[mt][nt][0] * i0, acc[mt][nt][1] * i0);
            float2 v1 = make_float2(acc[mt][nt][2] * i1, acc[mt][nt][3] * i1);
            *reinterpret_cast<float2*>(z0 + col) = v0;
            *reinterpret_cast<float2*>(z0 + (size_t)8 * CC + col) = v1;
        }
    }
}

// ===========================================================================
// S2: e = (z/se) @ W + bias, zeroed where se==0.  M = BB*EE, K = CC.
// ===========================================================================
__global__ void __launch_bounds__(256, 1)
s2_kernel(const float* __restrict__ Wm, const float* __restrict__ bias) {
    const int m0 = blockIdx.x * BM;

    extern __shared__ float sm[];
    float* As = sm;                       // 2 * BM * LDMK ([m][k])
    float* Bs = sm + 2 * BM * LDMK;       // 2 * BK * LDB_
    __shared__ float s_b[CC];

    const int tid = threadIdx.x;
    const int lane = tid & 31, wid = tid >> 5;
    const int g = lane >> 2, tg = lane & 3;
    const int wm = (wid >> 1) * 32;
    const int wn = (wid & 1) * 64;

    if (tid < CC) s_b[tid] = bias[tid];

    float acc[2][8][4];
#pragma unroll
    for (int i = 0; i < 2; i++)
#pragma unroll
        for (int j = 0; j < 8; j++)
#pragma unroll
            for (int k = 0; k < 4; k++) acc[i][j][k] = 0.f;

    float4 ar[4], br[4];

    auto LDGA = [&](int k0) {
#pragma unroll
        for (int i = 0; i < 4; i++) {
            int idx = tid + i * 256;
            int m = idx >> 3, k4 = idx & 7;
            ar[i] = *reinterpret_cast<const float4*>(g_Z + (size_t)(m0 + m) * CC + k0 + k4 * 4);
        }
    };
    auto LDGB = [&](int k0) {
#pragma unroll
        for (int i = 0; i < 4; i++) {
            int idx = tid + i * 256;
            int k = idx >> 5, c4 = idx & 31;
            br[i] = *reinterpret_cast<const float4*>(Wm + (size_t)(k0 + k) * CC + c4 * 4);
        }
    };
    auto STS = [&](int buf) {
        float* Ad = As + buf * BM * LDMK;
        float* Bd = Bs + buf * BK * LDB_;
#pragma unroll
        for (int i = 0; i < 4; i++) {
            int idx = tid + i * 256;
            int m = idx >> 3, k4 = idx & 7;
            float4 a = ar[i];
            a.x = tf32r(a.x); a.y = tf32r(a.y); a.z = tf32r(a.z); a.w = tf32r(a.w);
            *reinterpret_cast<float4*>(Ad + m * LDMK + k4 * 4) = a;
            int k = idx >> 5, c4 = idx & 31;
            float4 v = br[i];
            v.x = tf32r(v.x); v.y = tf32r(v.y); v.z = tf32r(v.z); v.w = tf32r(v.w);
            *reinterpret_cast<float4*>(Bd + k * LDB_ + c4 * 4) = v;
        }
    };
    auto COMPUTE = [&](int buf) {
        const float* Ab = As + buf * BM * LDMK;
        const float* Bb = Bs + buf * BK * LDB_;
#pragma unroll
        for (int kk = 0; kk < BK; kk += 8) {
            uint32_t af[2][4];
#pragma unroll
            for (int mt = 0; mt < 2; mt++) {
                const float* ap = Ab + (wm + mt * 16 + g) * LDMK + kk + tg;
                af[mt][0] = __float_as_uint(ap[0]);
                af[mt][1] = __float_as_uint(ap[8 * LDMK]);
                af[mt][2] = __float_as_uint(ap[4]);
                af[mt][3] = __float_as_uint(ap[8 * LDMK + 4]);
            }
#pragma unroll
            for (int nt = 0; nt < 8; nt++) {
                const float* bp = Bb + (kk + tg) * LDB_ + wn + nt * 8 + g;
                uint32_t b0 = __float_as_uint(bp[0]);
                uint32_t b1 = __float_as_uint(bp[4 * LDB_]);
                mma8(acc[0][nt][0], acc[0][nt][1], acc[0][nt][2], acc[0][nt][3],
                     af[0][0], af[0][1], af[0][2], af[0][3], b0, b1);
                mma8(acc[1][nt][0], acc[1][nt][1], acc[1][nt][2], acc[1][nt][3],
                     af[1][0], af[1][1], af[1][2], af[1][3], b0, b1);
            }
        }
    };

    LDGA(0); LDGB(0); STS(0); __syncthreads();
    int buf = 0;
    const int KT = CC / BK;
    for (int kt = 0; kt < KT; kt++) {
        if (kt + 1 < KT) { LDGA((kt + 1) * BK); LDGB((kt + 1) * BK); }
        COMPUTE(buf);
        if (kt + 1 < KT) {
            STS(buf ^ 1);
            __syncthreads();
            buf ^= 1;
        }
    }

#pragma unroll
    for (int mt = 0; mt < 2; mt++) {
        int r0 = wm + mt * 16 + g;
        int R0 = m0 + r0;
        bool m0ok = g_SE[R0] > 0.f;
        bool m1ok = g_SE[R0 + 8] > 0.f;
        float* ep = g_E + (size_t)R0 * CC;
#pragma unroll
        for (int nt = 0; nt < 8; nt++) {
            int col = wn + nt * 8 + 2 * tg;
            float b0v = s_b[col], b1v = s_b[col + 1];
            float2 v0 = make_float2(m0ok ? acc[mt][nt][0] + b0v : 0.f,
                                    m0ok ? acc[mt][nt][1] + b1v : 0.f);
            float2 v1 = make_float2(m1ok ? acc[mt][nt][2] + b0v : 0.f,
                                    m1ok ? acc[mt][nt][3] + b1v : 0.f);
            *reinterpret_cast<float2*>(ep + col) = v0;
            *reinterpret_cast<float2*>(ep + (size_t)8 * CC + col) = v1;
        }
    }
}

// ===========================================================================
// S3: v[b,n,:] = (sum_e H[b,n,e] * e[b,e,:]) / sv[b,n]   (sv from A-frags)
// ===========================================================================
__global__ void __launch_bounds__(256, 1)
s3_kernel(const float* __restrict__ H, float* __restrict__ out) {
    const int b  = blockIdx.y;
    const int n0 = blockIdx.x * BM;

    extern __shared__ float sm[];
    float* As = sm;                       // 2 * BM * LDMK ([m][k])
    float* Bs = sm + 2 * BM * LDMK;       // 2 * BK * LDB_
    __shared__ float s_rs[BM];
    __shared__ float s_inv[BM];

    const int tid = threadIdx.x;
    const int lane = tid & 31, wid = tid >> 5;
    const int g = lane >> 2, tg = lane & 3;
    const int wm = (wid >> 1) * 32;
    const int wn = (wid & 1) * 64;

    const float* Hb = H + (size_t)b * NN * EE;

    float acc[2][8][4];
#pragma unroll
    for (int i = 0; i < 2; i++)
#pragma unroll
        for (int j = 0; j < 8; j++)
#pragma unroll
            for (int k = 0; k < 4; k++) acc[i][j][k] = 0.f;
    float rs[2][2] = {{0.f, 0.f}, {0.f, 0.f}};

    float4 ar[4], br[4];

    auto LDGA = [&](int k0) {
#pragma unroll
        for (int i = 0; i < 4; i++) {
            int idx = tid + i * 256;
            int m = idx >> 3, k4 = idx & 7;
            ar[i] = *reinterpret_cast<const float4*>(Hb + (size_t)(n0 + m) * EE + k0 + k4 * 4);
        }
    };
    auto LDGB = [&](int k0) {
#pragma unroll
        for (int i = 0; i < 4; i++) {
            int idx = tid + i * 256;
            int k = idx >> 5, c4 = idx & 31;
            br[i] = *reinterpret_cast<const float4*>(g_E + (size_t)(b * EE + k0 + k) * CC + c4 * 4);
        }
    };
    auto STS = [&](int buf) {
        float* Ad = As + buf * BM * LDMK;
        float* Bd = Bs + buf * BK * LDB_;
#pragma unroll
        for (int i = 0; i < 4; i++) {
            int idx = tid + i * 256;
            int m = idx >> 3, k4 = idx & 7;
            *reinterpret_cast<float4*>(Ad + m * LDMK + k4 * 4) = ar[i];  // H exact
            int k = idx >> 5, c4 = idx & 31;
            float4 v = br[i];
            v.x = tf32r(v.x); v.y = tf32r(v.y); v.z = tf32r(v.z); v.w = tf32r(v.w);
            *reinterpret_cast<float4*>(Bd + k * LDB_ + c4 * 4) = v;
        }
    };
    auto COMPUTE = [&](int buf) {
        const float* Ab = As + buf * BM * LDMK;
        const float* Bb = Bs + buf * BK * LDB_;
#pragma unroll
        for (int kk = 0; kk < BK; kk += 8) {
            uint32_t af[2][4];
#pragma unroll
            for (int mt = 0; mt < 2; mt++) {
                const float* ap = Ab + (wm + mt * 16 + g) * LDMK + kk + tg;
                af[mt][0] = __float_as_uint(ap[0]);
                af[mt][1] = __float_as_uint(ap[8 * LDMK]);
                af[mt][2] = __float_as_uint(ap[4]);
                af[mt][3] = __float_as_uint(ap[8 * LDMK + 4]);
            }
            if ((wid & 1) == 0) {
#pragma unroll
                for (int mt = 0; mt < 2; mt++) {
                    rs[mt][0] += __uint_as_float(af[mt][0]) + __uint_as_float(af[mt][2]);
                    rs[mt][1] += __uint_as_float(af[mt][1]) + __uint_as_float(af[mt][3]);
                }
            }
#pragma unroll
            for (int nt = 0; nt < 8; nt++) {
                const float* bp = Bb + (kk + tg) * LDB_ + wn + nt * 8 + g;
                uint32_t b0 = __float_as_uint(bp[0]);
                uint32_t b1 = __float_as_uint(bp[4 * LDB_]);
                mma8(acc[0][nt][0], acc[0][nt][1], acc[0][nt][2], acc[0][nt][3],
                     af[0][0], af[0][1], af[0][2], af[0][3], b0, b1);
                mma8(acc[1][nt][0], acc[1][nt][1], acc[1][nt][2], acc[1][nt][3],
                     af[1][0], af[1][1], af[1][2], af[1][3], b0, b1);
            }
        }
    };

    LDGA(0); LDGB(0); STS(0); __syncthreads();
    int buf = 0;
    const int KT = EE / BK;
    for (int kt = 0; kt < KT; kt++) {
        if (kt + 1 < KT) { LDGA((kt + 1) * BK); LDGB((kt + 1) * BK); }
        COMPUTE(buf);
        if (kt + 1 < KT) {
            STS(buf ^ 1);
            __syncthreads();
            buf ^= 1;
        }
    }

    if ((wid & 1) == 0) {
#pragma unroll
        for (int mt = 0; mt < 2; mt++)
#pragma unroll
            for (int j = 0; j < 2; j++) {
                float v = rs[mt][j];
                v += __shfl_xor_sync(0xffffffff, v, 1);
                v += __shfl_xor_sync(0xffffffff, v, 2);
                if (tg == 0) s_rs[wm + mt * 16 + j * 8 + g] = v;
            }
    }
    __syncthreads();
    if (tid < BM) {
        float s = s_rs[tid];
        s_inv[tid] = (s > 0.f) ? (1.0f / s) : 0.f;
    }
    __syncthreads();

#pragma unroll
    for (int mt = 0; mt < 2; mt++) {
        int r0 = wm + mt * 16 + g;
        float i0 = s_inv[r0], i1 = s_inv[r0 + 8];
        float* op = out + ((size_t)(b * NN + n0 + r0)) * CC;
#pragma unroll
        for (int nt = 0; nt < 8; nt++) {
            int col = wn + nt * 8 + 2 * tg;
            float2 v0 = make_float2(acc[mt][nt][0] * i0, acc[mt][nt][1] * i0);
            float2 v1 = make_float2(acc[mt][nt][2] * i1, acc[mt][nt][3] * i1);
            *reinterpret_cast<float2*>(op + col) = v0;
            *reinterpret_cast<float2*>(op + (size_t)8 * CC + col) = v1;
        }
    }
}

// ===========================================================================
extern "C" void kernel_launch(void* const* d_in, const int* in_sizes, int n_in,
                              void* d_out, int out_size) {
    // Identify inputs by element count (robust to ordering)
    const float* X = nullptr;   // 8*4096*128  = 4194304
    const float* H = nullptr;   // 8*4096*2048 = 67108864
    const float* W = nullptr;   // 128*128     = 16384
    const float* bias = nullptr;// 128
    for (int i = 0; i < n_in; i++) {
        if (in_sizes[i] == BB * NN * CC)      X = (const float*)d_in[i];
        else if (in_sizes[i] == BB * NN * EE) H = (const float*)d_in[i];
        else if (in_sizes[i] == CC * CC)      W = (const float*)d_in[i];
        else if (in_sizes[i] == CC)           bias = (const float*)d_in[i];
    }
    float* out = (float*)d_out;

    const int smem1  = (2 * BK * LDKM + 2 * BK * LDB_) * (int)sizeof(float);   // ~68 KB
    const int smem23 = (2 * BM * LDMK + 2 * BK * LDB_) * (int)sizeof(float);   // ~70 KB
    cudaFuncSetAttribute(s1_kernel, cudaFuncAttributeMaxDynamicSharedMemorySize, smem1);
    cudaFuncSetAttribute(s2_kernel, cudaFuncAttributeMaxDynamicSharedMemorySize, smem23);
    cudaFuncSetAttribute(s3_kernel, cudaFuncAttributeMaxDynamicSharedMemorySize, smem23);

    s1_kernel<<<dim3(EE / BM, BB), 256, smem1>>>(H, X);
    s2_kernel<<<dim3((BB * EE) / BM), 256, smem23>>>(W, bias);
    s3_kernel<<<dim3(NN / BM, BB), 256, smem23>>>(H, out);
}

// round 6
// speedup vs baseline: 1.0001x; 1.0001x over previous
#include <cuda_runtime.h>
#include <cstdint>
#include <cstddef>

// Problem shape (fixed)
#define BB 8
#define NN 4096
#define EE 2048
#define CC 128

// Scratch (no cudaMalloc allowed)
__device__ float g_Z[BB * EE * CC];   // z/se  (scaled v2e aggregate, pre-projection)
__device__ float g_E[BB * EE * CC];   // e     (edge features)
__device__ float g_SE[BB * EE];       // se    (edge degree)

// GEMM tiling
#define BM 128
#define BN 128
#define BK 32
#define LDKM 136   // As stored [k][m], pad 8 -> conflict-free a-frag loads
#define LDMK 36    // As stored [m][k], pad 4 -> conflict-free a-frag loads
#define LDB_ 136   // Bs stored [k][n], pad 8 -> conflict-free b-frag loads

__device__ __forceinline__ float tf32r(float x) {
    // round-to-nearest tf32 (unbiased; truncation bias would blow the error budget)
    uint32_t u;
    asm("cvt.rna.tf32.f32 %0, %1;" : "=r"(u) : "f"(x));
    return __uint_as_float(u);
}

__device__ __forceinline__ void mma8(float& d0, float& d1, float& d2, float& d3,
                                     uint32_t a0, uint32_t a1, uint32_t a2, uint32_t a3,
                                     uint32_t b0, uint32_t b1) {
    asm volatile(
        "mma.sync.aligned.m16n8k8.row.col.f32.tf32.tf32.f32 "
        "{%0,%1,%2,%3},{%4,%5,%6,%7},{%8,%9},{%0,%1,%2,%3};"
        : "+f"(d0), "+f"(d1), "+f"(d2), "+f"(d3)
        : "r"(a0), "r"(a1), "r"(a2), "r"(a3), "r"(b0), "r"(b1));
}

// ===========================================================================
// S1: z[b,e,:] = sum_n H[b,n,e] * x[b,n,:]   (A = H^T, K-major in gmem)
//     se[b,e]  = sum_n H[b,n,e]              (free from A-fragments)
//     g_Z stores z/se (guarded), g_SE stores se.
// ===========================================================================
__global__ void __launch_bounds__(256, 1)
s1_kernel(const float* __restrict__ H, const float* __restrict__ X) {
    const int b  = blockIdx.y;
    const int e0 = blockIdx.x * BM;

    extern __shared__ float sm[];
    float* As = sm;                       // 2 * BK * LDKM  ([k][m])
    float* Bs = sm + 2 * BK * LDKM;       // 2 * BK * LDB_  ([k][n])
    __shared__ float s_rs[BM];
    __shared__ float s_inv[BM];

    const int tid = threadIdx.x;
    const int lane = tid & 31, wid = tid >> 5;
    const int g = lane >> 2, tg = lane & 3;
    const int wm = (wid >> 1) * 32;
    const int wn = (wid & 1) * 64;

    const float* Hb = H + (size_t)b * NN * EE;
    const float* Xb = X + (size_t)b * NN * CC;

    float acc[2][8][4];
#pragma unroll
    for (int i = 0; i < 2; i++)
#pragma unroll
        for (int j = 0; j < 8; j++)
#pragma unroll
            for (int k = 0; k < 4; k++) acc[i][j][k] = 0.f;
    float rs[2][2] = {{0.f, 0.f}, {0.f, 0.f}};

    float4 ar[4], br[4];

    auto LDGA = [&](int n0) {
#pragma unroll
        for (int i = 0; i < 4; i++) {
            int idx = tid + i * 256;
            int k = idx >> 5, m4 = idx & 31;
            ar[i] = *reinterpret_cast<const float4*>(Hb + (size_t)(n0 + k) * EE + e0 + m4 * 4);
        }
    };
    auto LDGB = [&](int n0) {
#pragma unroll
        for (int i = 0; i < 4; i++) {
            int idx = tid + i * 256;
            int k = idx >> 5, c4 = idx & 31;
            br[i] = *reinterpret_cast<const float4*>(Xb + (size_t)(n0 + k) * CC + c4 * 4);
        }
    };
    auto STS = [&](int buf) {
        float* Ad = As + buf * BK * LDKM;
        float* Bd = Bs + buf * BK * LDB_;
#pragma unroll
        for (int i = 0; i < 4; i++) {
            int idx = tid + i * 256;
            int k = idx >> 5, m4 = idx & 31;
            *reinterpret_cast<float4*>(Ad + k * LDKM + m4 * 4) = ar[i];  // H exact, no cvt
            float4 v = br[i];
            v.x = tf32r(v.x); v.y = tf32r(v.y); v.z = tf32r(v.z); v.w = tf32r(v.w);
            *reinterpret_cast<float4*>(Bd + k * LDB_ + m4 * 4) = v;
        }
    };
    auto COMPUTE = [&](int buf) {
        const float* Ab = As + buf * BK * LDKM;
        const float* Bb = Bs + buf * BK * LDB_;
#pragma unroll
        for (int kk = 0; kk < BK; kk += 8) {
            uint32_t af[2][4];
#pragma unroll
            for (int mt = 0; mt < 2; mt++) {
                const float* ap = Ab + (kk + tg) * LDKM + wm + mt * 16 + g;
                af[mt][0] = __float_as_uint(ap[0]);
                af[mt][1] = __float_as_uint(ap[8]);
                af[mt][2] = __float_as_uint(ap[4 * LDKM]);
                af[mt][3] = __float_as_uint(ap[4 * LDKM + 8]);
            }
            if ((wid & 1) == 0) {  // count each H element once (wn==0 warps)
#pragma unroll
                for (int mt = 0; mt < 2; mt++) {
                    rs[mt][0] += __uint_as_float(af[mt][0]) + __uint_as_float(af[mt][2]);
                    rs[mt][1] += __uint_as_float(af[mt][1]) + __uint_as_float(af[mt][3]);
                }
            }
#pragma unroll
            for (int nt = 0; nt < 8; nt++) {
                const float* bp = Bb + (kk + tg) * LDB_ + wn + nt * 8 + g;
                uint32_t b0 = __float_as_uint(bp[0]);
                uint32_t b1 = __float_as_uint(bp[4 * LDB_]);
                mma8(acc[0][nt][0], acc[0][nt][1], acc[0][nt][2], acc[0][nt][3],
                     af[0][0], af[0][1], af[0][2], af[0][3], b0, b1);
                mma8(acc[1][nt][0], acc[1][nt][1], acc[1][nt][2], acc[1][nt][3],
                     af[1][0], af[1][1], af[1][2], af[1][3], b0, b1);
            }
        }
    };

    LDGA(0); LDGB(0); STS(0); __syncthreads();
    int buf = 0;
    const int KT = NN / BK;
    for (int kt = 0; kt < KT; kt++) {
        if (kt + 1 < KT) { LDGA((kt + 1) * BK); LDGB((kt + 1) * BK); }
        COMPUTE(buf);
        if (kt + 1 < KT) {
            STS(buf ^ 1);
            __syncthreads();
            buf ^= 1;
        }
    }

    // se: quad-reduce row sums
    if ((wid & 1) == 0) {
#pragma unroll
        for (int mt = 0; mt < 2; mt++)
#pragma unroll
            for (int j = 0; j < 2; j++) {
                float v = rs[mt][j];
                v += __shfl_xor_sync(0xffffffff, v, 1);
                v += __shfl_xor_sync(0xffffffff, v, 2);
                if (tg == 0) s_rs[wm + mt * 16 + j * 8 + g] = v;
            }
    }
    __syncthreads();
    if (tid < BM) {
        float s = s_rs[tid];
        g_SE[b * EE + e0 + tid] = s;
        s_inv[tid] = (s > 0.f) ? (1.0f / s) : 0.f;
    }
    __syncthreads();

#pragma unroll
    for (int mt = 0; mt < 2; mt++) {
        int r0 = wm + mt * 16 + g;
        float i0 = s_inv[r0], i1 = s_inv[r0 + 8];
        float* z0 = g_Z + ((size_t)(b * EE + e0 + r0)) * CC;
#pragma unroll
        for (int nt = 0; nt < 8; nt++) {
            int col = wn + nt * 8 + 2 * tg;
            float2 v0 = make_float2(acc[mt][nt][0] * i0, acc[mt][nt][1] * i0);
            float2 v1 = make_float2(acc[mt][nt][2] * i1, acc[mt][nt][3] * i1);
            *reinterpret_cast<float2*>(z0 + col) = v0;
            *reinterpret_cast<float2*>(z0 + (size_t)8 * CC + col) = v1;
        }
    }
}

// ===========================================================================
// S2: e = (z/se) @ W + bias, zeroed where se==0.  M = BB*EE, K = CC.
// ===========================================================================
__global__ void __launch_bounds__(256, 1)
s2_kernel(const float* __restrict__ Wm, const float* __restrict__ bias) {
    const int m0 = blockIdx.x * BM;

    extern __shared__ float sm[];
    float* As = sm;                       // 2 * BM * LDMK ([m][k])
    float* Bs = sm + 2 * BM * LDMK;       // 2 * BK * LDB_
    __shared__ float s_b[CC];

    const int tid = threadIdx.x;
    const int lane = tid & 31, wid = tid >> 5;
    const int g = lane >> 2, tg = lane & 3;
    const int wm = (wid >> 1) * 32;
    const int wn = (wid & 1) * 64;

    if (tid < CC) s_b[tid] = bias[tid];

    float acc[2][8][4];
#pragma unroll
    for (int i = 0; i < 2; i++)
#pragma unroll
        for (int j = 0; j < 8; j++)
#pragma unroll
            for (int k = 0; k < 4; k++) acc[i][j][k] = 0.f;

    float4 ar[4], br[4];

    auto LDGA = [&](int k0) {
#pragma unroll
        for (int i = 0; i < 4; i++) {
            int idx = tid + i * 256;
            int m = idx >> 3, k4 = idx & 7;
            ar[i] = *reinterpret_cast<const float4*>(g_Z + (size_t)(m0 + m) * CC + k0 + k4 * 4);
        }
    };
    auto LDGB = [&](int k0) {
#pragma unroll
        for (int i = 0; i < 4; i++) {
            int idx = tid + i * 256;
            int k = idx >> 5, c4 = idx & 31;
            br[i] = *reinterpret_cast<const float4*>(Wm + (size_t)(k0 + k) * CC + c4 * 4);
        }
    };
    auto STS = [&](int buf) {
        float* Ad = As + buf * BM * LDMK;
        float* Bd = Bs + buf * BK * LDB_;
#pragma unroll
        for (int i = 0; i < 4; i++) {
            int idx = tid + i * 256;
            int m = idx >> 3, k4 = idx & 7;
            float4 a = ar[i];
            a.x = tf32r(a.x); a.y = tf32r(a.y); a.z = tf32r(a.z); a.w = tf32r(a.w);
            *reinterpret_cast<float4*>(Ad + m * LDMK + k4 * 4) = a;
            int k = idx >> 5, c4 = idx & 31;
            float4 v = br[i];
            v.x = tf32r(v.x); v.y = tf32r(v.y); v.z = tf32r(v.z); v.w = tf32r(v.w);
            *reinterpret_cast<float4*>(Bd + k * LDB_ + c4 * 4) = v;
        }
    };
    auto COMPUTE = [&](int buf) {
        const float* Ab = As + buf * BM * LDMK;
        const float* Bb = Bs + buf * BK * LDB_;
#pragma unroll
        for (int kk = 0; kk < BK; kk += 8) {
            uint32_t af[2][4];
#pragma unroll
            for (int mt = 0; mt < 2; mt++) {
                const float* ap = Ab + (wm + mt * 16 + g) * LDMK + kk + tg;
                af[mt][0] = __float_as_uint(ap[0]);
                af[mt][1] = __float_as_uint(ap[8 * LDMK]);
                af[mt][2] = __float_as_uint(ap[4]);
                af[mt][3] = __float_as_uint(ap[8 * LDMK + 4]);
            }
#pragma unroll
            for (int nt = 0; nt < 8; nt++) {
                const float* bp = Bb + (kk + tg) * LDB_ + wn + nt * 8 + g;
                uint32_t b0 = __float_as_uint(bp[0]);
                uint32_t b1 = __float_as_uint(bp[4 * LDB_]);
                mma8(acc[0][nt][0], acc[0][nt][1], acc[0][nt][2], acc[0][nt][3],
                     af[0][0], af[0][1], af[0][2], af[0][3], b0, b1);
                mma8(acc[1][nt][0], acc[1][nt][1], acc[1][nt][2], acc[1][nt][3],
                     af[1][0], af[1][1], af[1][2], af[1][3], b0, b1);
            }
        }
    };

    LDGA(0); LDGB(0); STS(0); __syncthreads();
    int buf = 0;
    const int KT = CC / BK;
    for (int kt = 0; kt < KT; kt++) {
        if (kt + 1 < KT) { LDGA((kt + 1) * BK); LDGB((kt + 1) * BK); }
        COMPUTE(buf);
        if (kt + 1 < KT) {
            STS(buf ^ 1);
            __syncthreads();
            buf ^= 1;
        }
    }

#pragma unroll
    for (int mt = 0; mt < 2; mt++) {
        int r0 = wm + mt * 16 + g;
        int R0 = m0 + r0;
        bool m0ok = g_SE[R0] > 0.f;
        bool m1ok = g_SE[R0 + 8] > 0.f;
        float* ep = g_E + (size_t)R0 * CC;
#pragma unroll
        for (int nt = 0; nt < 8; nt++) {
            int col = wn + nt * 8 + 2 * tg;
            float b0v = s_b[col], b1v = s_b[col + 1];
            float2 v0 = make_float2(m0ok ? acc[mt][nt][0] + b0v : 0.f,
                                    m0ok ? acc[mt][nt][1] + b1v : 0.f);
            float2 v1 = make_float2(m1ok ? acc[mt][nt][2] + b0v : 0.f,
                                    m1ok ? acc[mt][nt][3] + b1v : 0.f);
            *reinterpret_cast<float2*>(ep + col) = v0;
            *reinterpret_cast<float2*>(ep + (size_t)8 * CC + col) = v1;
        }
    }
}

// ===========================================================================
// S3: v[b,n,:] = (sum_e H[b,n,e] * e[b,e,:]) / sv[b,n]   (sv from A-frags)
// ===========================================================================
__global__ void __launch_bounds__(256, 1)
s3_kernel(const float* __restrict__ H, float* __restrict__ out) {
    const int b  = blockIdx.y;
    const int n0 = blockIdx.x * BM;

    extern __shared__ float sm[];
    float* As = sm;                       // 2 * BM * LDMK ([m][k])
    float* Bs = sm + 2 * BM * LDMK;       // 2 * BK * LDB_
    __shared__ float s_rs[BM];
    __shared__ float s_inv[BM];

    const int tid = threadIdx.x;
    const int lane = tid & 31, wid = tid >> 5;
    const int g = lane >> 2, tg = lane & 3;
    const int wm = (wid >> 1) * 32;
    const int wn = (wid & 1) * 64;

    const float* Hb = H + (size_t)b * NN * EE;

    float acc[2][8][4];
#pragma unroll
    for (int i = 0; i < 2; i++)
#pragma unroll
        for (int j = 0; j < 8; j++)
#pragma unroll
            for (int k = 0; k < 4; k++) acc[i][j][k] = 0.f;
    float rs[2][2] = {{0.f, 0.f}, {0.f, 0.f}};

    float4 ar[4], br[4];

    auto LDGA = [&](int k0) {
#pragma unroll
        for (int i = 0; i < 4; i++) {
            int idx = tid + i * 256;
            int m = idx >> 3, k4 = idx & 7;
            ar[i] = *reinterpret_cast<const float4*>(Hb + (size_t)(n0 + m) * EE + k0 + k4 * 4);
        }
    };
    auto LDGB = [&](int k0) {
#pragma unroll
        for (int i = 0; i < 4; i++) {
            int idx = tid + i * 256;
            int k = idx >> 5, c4 = idx & 31;
            br[i] = *reinterpret_cast<const float4*>(g_E + (size_t)(b * EE + k0 + k) * CC + c4 * 4);
        }
    };
    auto STS = [&](int buf) {
        float* Ad = As + buf * BM * LDMK;
        float* Bd = Bs + buf * BK * LDB_;
#pragma unroll
        for (int i = 0; i < 4; i++) {
            int idx = tid + i * 256;
            int m = idx >> 3, k4 = idx & 7;
            *reinterpret_cast<float4*>(Ad + m * LDMK + k4 * 4) = ar[i];  // H exact
            int k = idx >> 5, c4 = idx & 31;
            float4 v = br[i];
            v.x = tf32r(v.x); v.y = tf32r(v.y); v.z = tf32r(v.z); v.w = tf32r(v.w);
            *reinterpret_cast<float4*>(Bd + k * LDB_ + c4 * 4) = v;
        }
    };
    auto COMPUTE = [&](int buf) {
        const float* Ab = As + buf * BM * LDMK;
        const float* Bb = Bs + buf * BK * LDB_;
#pragma unroll
        for (int kk = 0; kk < BK; kk += 8) {
            uint32_t af[2][4];
#pragma unroll
            for (int mt = 0; mt < 2; mt++) {
                const float* ap = Ab + (wm + mt * 16 + g) * LDMK + kk + tg;
                af[mt][0] = __float_as_uint(ap[0]);
                af[mt][1] = __float_as_uint(ap[8 * LDMK]);
                af[mt][2] = __float_as_uint(ap[4]);
                af[mt][3] = __float_as_uint(ap[8 * LDMK + 4]);
            }
            if ((wid & 1) == 0) {
#pragma unroll
                for (int mt = 0; mt < 2; mt++) {
                    rs[mt][0] += __uint_as_float(af[mt][0]) + __uint_as_float(af[mt][2]);
                    rs[mt][1] += __uint_as_float(af[mt][1]) + __uint_as_float(af[mt][3]);
                }
            }
#pragma unroll
            for (int nt = 0; nt < 8; nt++) {
                const float* bp = Bb + (kk + tg) * LDB_ + wn + nt * 8 + g;
                uint32_t b0 = __float_as_uint(bp[0]);
                uint32_t b1 = __float_as_uint(bp[4 * LDB_]);
                mma8(acc[0][nt][0], acc[0][nt][1], acc[0][nt][2], acc[0][nt][3],
                     af[0][0], af[0][1], af[0][2], af[0][3], b0, b1);
                mma8(acc[1][nt][0], acc[1][nt][1], acc[1][nt][2], acc[1][nt][3],
                     af[1][0], af[1][1], af[1][2], af[1][3], b0, b1);
            }
        }
    };

    LDGA(0); LDGB(0); STS(0); __syncthreads();
    int buf = 0;
    const int KT = EE / BK;
    for (int kt = 0; kt < KT; kt++) {
        if (kt + 1 < KT) { LDGA((kt + 1) * BK); LDGB((kt + 1) * BK); }
        COMPUTE(buf);
        if (kt + 1 < KT) {
            STS(buf ^ 1);
            __syncthreads();
            buf ^= 1;
        }
    }

    if ((wid & 1) == 0) {
#pragma unroll
        for (int mt = 0; mt < 2; mt++)
#pragma unroll
            for (int j = 0; j < 2; j++) {
                float v = rs[mt][j];
                v += __shfl_xor_sync(0xffffffff, v, 1);
                v += __shfl_xor_sync(0xffffffff, v, 2);
                if (tg == 0) s_rs[wm + mt * 16 + j * 8 + g] = v;
            }
    }
    __syncthreads();
    if (tid < BM) {
        float s = s_rs[tid];
        s_inv[tid] = (s > 0.f) ? (1.0f / s) : 0.f;
    }
    __syncthreads();

#pragma unroll
    for (int mt = 0; mt < 2; mt++) {
        int r0 = wm + mt * 16 + g;
        float i0 = s_inv[r0], i1 = s_inv[r0 + 8];
        float* op = out + ((size_t)(b * NN + n0 + r0)) * CC;
#pragma unroll
        for (int nt = 0; nt < 8; nt++) {
            int col = wn + nt * 8 + 2 * tg;
            float2 v0 = make_float2(acc[mt][nt][0] * i0, acc[mt][nt][1] * i0);
            float2 v1 = make_float2(acc[mt][nt][2] * i1, acc[mt][nt][3] * i1);
            *reinterpret_cast<float2*>(op + col) = v0;
            *reinterpret_cast<float2*>(op + (size_t)8 * CC + col) = v1;
        }
    }
}

// ===========================================================================
extern "C" void kernel_launch(void* const* d_in, const int* in_sizes, int n_in,
                              void* d_out, int out_size) {
    // Identify inputs by element count (robust to ordering)
    const float* X = nullptr;   // 8*4096*128  = 4194304
    const float* H = nullptr;   // 8*4096*2048 = 67108864
    const float* W = nullptr;   // 128*128     = 16384
    const float* bias = nullptr;// 128
    for (int i = 0; i < n_in; i++) {
        if (in_sizes[i] == BB * NN * CC)      X = (const float*)d_in[i];
        else if (in_sizes[i] == BB * NN * EE) H = (const float*)d_in[i];
        else if (in_sizes[i] == CC * CC)      W = (const float*)d_in[i];
        else if (in_sizes[i] == CC)           bias = (const float*)d_in[i];
    }
    float* out = (float*)d_out;

    const int smem1  = (2 * BK * LDKM + 2 * BK * LDB_) * (int)sizeof(float);   // ~68 KB
    const int smem23 = (2 * BM * LDMK + 2 * BK * LDB_) * (int)sizeof(float);   // ~70 KB
    cudaFuncSetAttribute(s1_kernel, cudaFuncAttributeMaxDynamicSharedMemorySize, smem1);
    cudaFuncSetAttribute(s2_kernel, cudaFuncAttributeMaxDynamicSharedMemorySize, smem23);
    cudaFuncSetAttribute(s3_kernel, cudaFuncAttributeMaxDynamicSharedMemorySize, smem23);

    s1_kernel<<<dim3(EE / BM, BB), 256, smem1>>>(H, X);
    s2_kernel<<<dim3((BB * EE) / BM), 256, smem23>>>(W, bias);
    s3_kernel<<<dim3(NN / BM, BB), 256, smem23>>>(H, out);
}